// round 1
// baseline (speedup 1.0000x reference)
#include <cuda_runtime.h>
#include <math.h>

#define S_LEN 2048
#define D_MODEL 2048
#define N_HEADS 16
#define HEAD_DIM 64   // pair count per head for rope (half of 128)
#define HD 128
#define E3 (3 * D_MODEL)   // 6144

// ---------------- scratch (static device globals; no allocations) -------------
__device__ float g_qkv[(size_t)S_LEN * E3];                      // [2048, 6144]
__device__ float g_scores[(size_t)N_HEADS * S_LEN * S_LEN];      // [16, 2048, 2048]
__device__ float g_att[(size_t)S_LEN * D_MODEL];                 // [2048, 2048]

// ---------------- GEMM NT: C[m,n] = scale * sum_k A[m,k] * B[n,k] --------------
// 128x128 block, BK=8, 256 threads, 8x8 microtile per thread.
__global__ void __launch_bounds__(256) gemm_nt_kernel(
    const float* __restrict__ A, const float* __restrict__ B, float* __restrict__ C,
    int K, int lda, int ldb, int ldc,
    long long aStrideZ, long long bStrideZ, long long cStrideZ, float scale)
{
    __shared__ float As[8][128];
    __shared__ float Bs[8][128];

    const long long z = blockIdx.z;
    A += z * aStrideZ;
    B += z * bStrideZ;
    C += z * cStrideZ;

    const int m0 = blockIdx.y * 128;
    const int n0 = blockIdx.x * 128;
    const int tid = threadIdx.x;
    const int tx = tid & 15;        // 0..15 -> 8 output cols
    const int ty = tid >> 4;        // 0..15 -> 8 output rows

    const int lk = tid & 7;         // k within BK tile
    const int lr = tid >> 3;        // 0..31, rows lr + {0,32,64,96}

    float acc[8][8];
#pragma unroll
    for (int i = 0; i < 8; i++)
#pragma unroll
        for (int j = 0; j < 8; j++) acc[i][j] = 0.0f;

    const float* Ap = A + (long long)(m0 + lr) * lda + lk;
    const float* Bp = B + (long long)(n0 + lr) * ldb + lk;

    for (int k0 = 0; k0 < K; k0 += 8) {
#pragma unroll
        for (int i = 0; i < 4; i++) {
            As[lk][lr + i * 32] = Ap[(long long)(i * 32) * lda + k0];
            Bs[lk][lr + i * 32] = Bp[(long long)(i * 32) * ldb + k0];
        }
        __syncthreads();
#pragma unroll
        for (int kk = 0; kk < 8; kk++) {
            float ra[8], rb[8];
#pragma unroll
            for (int i = 0; i < 8; i++) ra[i] = As[kk][ty * 8 + i];
#pragma unroll
            for (int j = 0; j < 8; j++) rb[j] = Bs[kk][tx * 8 + j];
#pragma unroll
            for (int i = 0; i < 8; i++)
#pragma unroll
                for (int j = 0; j < 8; j++)
                    acc[i][j] += ra[i] * rb[j];
        }
        __syncthreads();
    }

#pragma unroll
    for (int i = 0; i < 8; i++) {
        const long long m = m0 + ty * 8 + i;
#pragma unroll
        for (int j = 0; j < 8; j++) {
            C[m * ldc + n0 + tx * 8 + j] = acc[i][j] * scale;
        }
    }
}

// ---------------- GEMM NN: C[m,n] = sum_k A[m,k] * B[k,n] ---------------------
// Same blocking; B tile loaded n-contiguous (coalesced).
__global__ void __launch_bounds__(256) gemm_nn_kernel(
    const float* __restrict__ A, const float* __restrict__ B, float* __restrict__ C,
    int K, int lda, int ldb, int ldc,
    long long aStrideZ, long long bStrideZ, long long cStrideZ)
{
    __shared__ float As[8][128];
    __shared__ float Bs[8][128];

    const long long z = blockIdx.z;
    A += z * aStrideZ;
    B += z * bStrideZ;
    C += z * cStrideZ;

    const int m0 = blockIdx.y * 128;
    const int n0 = blockIdx.x * 128;
    const int tid = threadIdx.x;
    const int tx = tid & 15;
    const int ty = tid >> 4;

    const int lk = tid & 7;         // A: k within tile
    const int lr = tid >> 3;        // A: row base
    const int bn = tid & 127;       // B: col within tile
    const int bk = tid >> 7;        // B: row base (0..1), rows bk + {0,2,4,6}

    float acc[8][8];
#pragma unroll
    for (int i = 0; i < 8; i++)
#pragma unroll
        for (int j = 0; j < 8; j++) acc[i][j] = 0.0f;

    for (int k0 = 0; k0 < K; k0 += 8) {
#pragma unroll
        for (int i = 0; i < 4; i++) {
            As[lk][lr + i * 32] = A[(long long)(m0 + lr + i * 32) * lda + k0 + lk];
            Bs[bk + i * 2][bn]  = B[(long long)(k0 + bk + i * 2) * ldb + n0 + bn];
        }
        __syncthreads();
#pragma unroll
        for (int kk = 0; kk < 8; kk++) {
            float ra[8], rb[8];
#pragma unroll
            for (int i = 0; i < 8; i++) ra[i] = As[kk][ty * 8 + i];
#pragma unroll
            for (int j = 0; j < 8; j++) rb[j] = Bs[kk][tx * 8 + j];
#pragma unroll
            for (int i = 0; i < 8; i++)
#pragma unroll
                for (int j = 0; j < 8; j++)
                    acc[i][j] += ra[i] * rb[j];
        }
        __syncthreads();
    }

#pragma unroll
    for (int i = 0; i < 8; i++) {
        const long long m = m0 + ty * 8 + i;
#pragma unroll
        for (int j = 0; j < 8; j++) {
            C[m * ldc + n0 + tx * 8 + j] = acc[i][j];
        }
    }
}

// ---------------- RoPE (in place on q,k slices of g_qkv) ----------------------
__global__ void __launch_bounds__(1024) rope_kernel(float* __restrict__ qkv)
{
    __shared__ float s_inv[64];
    const int s = blockIdx.x;
    const int t = threadIdx.x;
    if (t < 64) {
        // inv_freq[j] = 10000^(-2j/128), computed in double for accuracy
        s_inv[t] = (float)pow(10000.0, -(double)(2 * t) / 128.0);
    }
    __syncthreads();

    const int h = t >> 6;      // 0..15
    const int j = t & 63;      // 0..63

    const float ang = (float)((double)s * (double)s_inv[j]);
    float sn, cs;
    sincosf(ang, &sn, &cs);

    float* q = qkv + (long long)s * E3 + h * HD;
    float* k = q + D_MODEL;

    const float q1 = q[j], q2 = q[j + 64];
    q[j]      = q1 * cs - q2 * sn;
    q[j + 64] = q2 * cs + q1 * sn;

    const float k1 = k[j], k2 = k[j + 64];
    k[j]      = k1 * cs - k2 * sn;
    k[j + 64] = k2 * cs + k1 * sn;
}

// ---------------- row softmax on scores ---------------------------------------
__global__ void __launch_bounds__(256) softmax_kernel(float* __restrict__ scores)
{
    const long long row = blockIdx.x;
    float* p = scores + row * S_LEN;
    const int t = threadIdx.x;
    const int lane = t & 31, warp = t >> 5;

    __shared__ float red[8];

    float v[8];
    float mx = -INFINITY;
#pragma unroll
    for (int i = 0; i < 8; i++) {
        v[i] = p[t + i * 256];
        mx = fmaxf(mx, v[i]);
    }
#pragma unroll
    for (int o = 16; o; o >>= 1) mx = fmaxf(mx, __shfl_xor_sync(0xffffffffu, mx, o));
    if (lane == 0) red[warp] = mx;
    __syncthreads();
    if (t < 32) {
        float x = (t < 8) ? red[t] : -INFINITY;
#pragma unroll
        for (int o = 4; o; o >>= 1) x = fmaxf(x, __shfl_xor_sync(0xffffffffu, x, o));
        if (t == 0) red[0] = x;
    }
    __syncthreads();
    mx = red[0];
    __syncthreads();

    float sum = 0.0f;
#pragma unroll
    for (int i = 0; i < 8; i++) {
        v[i] = __expf(v[i] - mx);
        sum += v[i];
    }
#pragma unroll
    for (int o = 16; o; o >>= 1) sum += __shfl_xor_sync(0xffffffffu, sum, o);
    if (lane == 0) red[warp] = sum;
    __syncthreads();
    if (t < 32) {
        float x = (t < 8) ? red[t] : 0.0f;
#pragma unroll
        for (int o = 4; o; o >>= 1) x += __shfl_xor_sync(0xffffffffu, x, o);
        if (t == 0) red[0] = x;
    }
    __syncthreads();
    const float r = 1.0f / red[0];
#pragma unroll
    for (int i = 0; i < 8; i++) p[t + i * 256] = v[i] * r;
}

// ---------------- launch -------------------------------------------------------
extern "C" void kernel_launch(void* const* d_in, const int* in_sizes, int n_in,
                              void* d_out, int out_size)
{
    (void)in_sizes; (void)n_in; (void)out_size;
    const float* x     = (const float*)d_in[0];   // [1, 2048, 2048]
    const float* w_qkv = (const float*)d_in[1];   // [6144, 2048]
    const float* w_out = (const float*)d_in[2];   // [2048, 2048]
    float* out = (float*)d_out;                   // [1, 2048, 2048]

    float* qkv;    cudaGetSymbolAddress((void**)&qkv,    g_qkv);
    float* scores; cudaGetSymbolAddress((void**)&scores, g_scores);
    float* att;    cudaGetSymbolAddress((void**)&att,    g_att);

    const float scale = 0.08838834764831845f;  // 1/sqrt(128)

    // 1) QKV projection: qkv[s,e] = sum_d x[s,d] * w_qkv[e,d]
    {
        dim3 grid(E3 / 128, S_LEN / 128, 1);
        gemm_nt_kernel<<<grid, 256>>>(x, w_qkv, qkv,
                                      D_MODEL, D_MODEL, D_MODEL, E3,
                                      0, 0, 0, 1.0f);
    }

    // 2) RoPE on q and k (in place)
    rope_kernel<<<S_LEN, 1024>>>(qkv);

    // 3) scores[h][q,k] = scale * sum_d Q_h[q,d] * K_h[k,d]
    {
        dim3 grid(S_LEN / 128, S_LEN / 128, N_HEADS);
        gemm_nt_kernel<<<grid, 256>>>(qkv, qkv + D_MODEL, scores,
                                      HD, E3, E3, S_LEN,
                                      HD, HD, (long long)S_LEN * S_LEN, scale);
    }

    // 4) softmax over last dim
    softmax_kernel<<<N_HEADS * S_LEN, 256>>>(scores);

    // 5) att_h = P_h @ V_h  -> att[s, h*128 + d]
    {
        dim3 grid(HD / 128, S_LEN / 128, N_HEADS);
        gemm_nn_kernel<<<grid, 256>>>(scores, qkv + 2 * D_MODEL, att,
                                      S_LEN, S_LEN, E3, D_MODEL,
                                      (long long)S_LEN * S_LEN, HD, HD);
    }

    // 6) out[s,o] = sum_d att[s,d] * w_out[o,d]
    {
        dim3 grid(D_MODEL / 128, S_LEN / 128, 1);
        gemm_nt_kernel<<<grid, 256>>>(att, w_out, out,
                                      D_MODEL, D_MODEL, D_MODEL, D_MODEL,
                                      0, 0, 0, 1.0f);
    }
}

// round 2
// speedup vs baseline: 1.4146x; 1.4146x over previous
#include <cuda_runtime.h>
#include <math.h>

#define S_LEN 2048
#define D_MODEL 2048
#define N_HEADS 16
#define HD 128
#define E3 (3 * D_MODEL)   // 6144

// ---------------- scratch (static device globals; no allocations) -------------
__device__ float g_qkv[(size_t)S_LEN * E3];                      // [2048, 6144]
__device__ float g_scores[(size_t)N_HEADS * S_LEN * S_LEN];      // [16, 2048, 2048]
__device__ float g_att[(size_t)S_LEN * D_MODEL];                 // [2048, 2048]

// =============================================================================
// SGEMM 128x128x16, 256 threads, 8x8 microtile, double-buffered smem,
// register-staged global loads, float4 LDG/LDS/STG.
// =============================================================================

#define BK 16
#define SMPAD 132   // row stride in floats (132 = 4*33: keeps float4 alignment, breaks conflicts)

// ---- NT: C[m,n] = scale * sum_k A[m,k] * B[n,k]  (A,B row-major, K contig) ----
__global__ void __launch_bounds__(256) gemm_nt_kernel(
    const float* __restrict__ A, const float* __restrict__ B, float* __restrict__ C,
    int K, int lda, int ldb, int ldc,
    long long aStrideZ, long long bStrideZ, long long cStrideZ, float scale)
{
    __shared__ __align__(16) float As[2][BK][SMPAD];
    __shared__ __align__(16) float Bs[2][BK][SMPAD];

    A += blockIdx.z * aStrideZ;
    B += blockIdx.z * bStrideZ;
    C += blockIdx.z * cStrideZ;

    const int m0 = blockIdx.y * 128;
    const int n0 = blockIdx.x * 128;
    const int tid = threadIdx.x;
    const int tx = tid & 15;        // col group
    const int ty = tid >> 4;        // row group

    // global load mapping: row = lrow (+64), float4 slot lk4 within 16-float k-strip
    const int lrow = tid >> 2;      // 0..63
    const int lk4  = tid & 3;       // 0..3
    const float* Ap = A + (long long)(m0 + lrow) * lda + lk4 * 4;
    const float* Bp = B + (long long)(n0 + lrow) * ldb + lk4 * 4;
    const long long a64 = (long long)64 * lda;
    const long long b64 = (long long)64 * ldb;

    float4 ra0, ra1, rb0, rb1;      // staged global data

#define LDG_TILE(k0)                                   \
    do {                                               \
        ra0 = *(const float4*)(Ap + (k0));             \
        ra1 = *(const float4*)(Ap + a64 + (k0));       \
        rb0 = *(const float4*)(Bp + (k0));             \
        rb1 = *(const float4*)(Bp + b64 + (k0));       \
    } while (0)

#define STS_TILE(buf)                                  \
    do {                                               \
        As[buf][lk4*4+0][lrow]      = ra0.x;           \
        As[buf][lk4*4+1][lrow]      = ra0.y;           \
        As[buf][lk4*4+2][lrow]      = ra0.z;           \
        As[buf][lk4*4+3][lrow]      = ra0.w;           \
        As[buf][lk4*4+0][lrow + 64] = ra1.x;           \
        As[buf][lk4*4+1][lrow + 64] = ra1.y;           \
        As[buf][lk4*4+2][lrow + 64] = ra1.z;           \
        As[buf][lk4*4+3][lrow + 64] = ra1.w;           \
        Bs[buf][lk4*4+0][lrow]      = rb0.x;           \
        Bs[buf][lk4*4+1][lrow]      = rb0.y;           \
        Bs[buf][lk4*4+2][lrow]      = rb0.z;           \
        Bs[buf][lk4*4+3][lrow]      = rb0.w;           \
        Bs[buf][lk4*4+0][lrow + 64] = rb1.x;           \
        Bs[buf][lk4*4+1][lrow + 64] = rb1.y;           \
        Bs[buf][lk4*4+2][lrow + 64] = rb1.z;           \
        Bs[buf][lk4*4+3][lrow + 64] = rb1.w;           \
    } while (0)

    float acc[8][8];
#pragma unroll
    for (int i = 0; i < 8; i++)
#pragma unroll
        for (int j = 0; j < 8; j++) acc[i][j] = 0.0f;

    const int ktiles = K / BK;
    LDG_TILE(0);
    STS_TILE(0);
    __syncthreads();

    int buf = 0;
    for (int t = 0; t < ktiles; t++) {
        if (t + 1 < ktiles) LDG_TILE((t + 1) * BK);
#pragma unroll
        for (int kk = 0; kk < BK; kk++) {
            float4 a0 = *(const float4*)&As[buf][kk][ty * 8];
            float4 a1 = *(const float4*)&As[buf][kk][ty * 8 + 4];
            float4 b0 = *(const float4*)&Bs[buf][kk][tx * 8];
            float4 b1 = *(const float4*)&Bs[buf][kk][tx * 8 + 4];
            float va[8] = {a0.x, a0.y, a0.z, a0.w, a1.x, a1.y, a1.z, a1.w};
            float vb[8] = {b0.x, b0.y, b0.z, b0.w, b1.x, b1.y, b1.z, b1.w};
#pragma unroll
            for (int i = 0; i < 8; i++)
#pragma unroll
                for (int j = 0; j < 8; j++)
                    acc[i][j] += va[i] * vb[j];
        }
        if (t + 1 < ktiles) {
            STS_TILE(buf ^ 1);
            __syncthreads();
            buf ^= 1;
        }
    }

#pragma unroll
    for (int i = 0; i < 8; i++) {
        const long long m = m0 + ty * 8 + i;
        float4 o0, o1;
        o0.x = acc[i][0] * scale; o0.y = acc[i][1] * scale;
        o0.z = acc[i][2] * scale; o0.w = acc[i][3] * scale;
        o1.x = acc[i][4] * scale; o1.y = acc[i][5] * scale;
        o1.z = acc[i][6] * scale; o1.w = acc[i][7] * scale;
        *(float4*)(C + m * ldc + n0 + tx * 8)     = o0;
        *(float4*)(C + m * ldc + n0 + tx * 8 + 4) = o1;
    }
#undef LDG_TILE
#undef STS_TILE
}

// ---- NN: C[m,n] = sum_k A[m,k] * B[k,n]  (B n-contiguous) --------------------
__global__ void __launch_bounds__(256) gemm_nn_kernel(
    const float* __restrict__ A, const float* __restrict__ B, float* __restrict__ C,
    int K, int lda, int ldb, int ldc,
    long long aStrideZ, long long bStrideZ, long long cStrideZ)
{
    __shared__ __align__(16) float As[2][BK][SMPAD];
    __shared__ __align__(16) float Bs[2][BK][SMPAD];

    A += blockIdx.z * aStrideZ;
    B += blockIdx.z * bStrideZ;
    C += blockIdx.z * cStrideZ;

    const int m0 = blockIdx.y * 128;
    const int n0 = blockIdx.x * 128;
    const int tid = threadIdx.x;
    const int tx = tid & 15;
    const int ty = tid >> 4;

    // A path: same as NT
    const int lrow = tid >> 2;
    const int lk4  = tid & 3;
    const float* Ap = A + (long long)(m0 + lrow) * lda + lk4 * 4;
    const long long a64 = (long long)64 * lda;

    // B path: tile is BK(16) rows x 128 cols, fully coalesced float4
    const int brow = tid >> 5;      // 0..7 (and +8)
    const int bc4  = tid & 31;      // float4 col
    const float* Bp = B + (long long)brow * ldb + bc4 * 4;
    const long long b8 = (long long)8 * ldb;

    float4 ra0, ra1, rb0, rb1;

#define LDG_TILE(k0)                                                  \
    do {                                                              \
        ra0 = *(const float4*)(Ap + (k0));                            \
        ra1 = *(const float4*)(Ap + a64 + (k0));                      \
        rb0 = *(const float4*)(Bp + (long long)(k0) * ldb + n0);      \
        rb1 = *(const float4*)(Bp + (long long)(k0) * ldb + b8 + n0); \
    } while (0)

#define STS_TILE(buf)                                  \
    do {                                               \
        As[buf][lk4*4+0][lrow]      = ra0.x;           \
        As[buf][lk4*4+1][lrow]      = ra0.y;           \
        As[buf][lk4*4+2][lrow]      = ra0.z;           \
        As[buf][lk4*4+3][lrow]      = ra0.w;           \
        As[buf][lk4*4+0][lrow + 64] = ra1.x;           \
        As[buf][lk4*4+1][lrow + 64] = ra1.y;           \
        As[buf][lk4*4+2][lrow + 64] = ra1.z;           \
        As[buf][lk4*4+3][lrow + 64] = ra1.w;           \
        *(float4*)&Bs[buf][brow][bc4 * 4]     = rb0;   \
        *(float4*)&Bs[buf][brow + 8][bc4 * 4] = rb1;   \
    } while (0)

    float acc[8][8];
#pragma unroll
    for (int i = 0; i < 8; i++)
#pragma unroll
        for (int j = 0; j < 8; j++) acc[i][j] = 0.0f;

    const int ktiles = K / BK;
    LDG_TILE(0);
    STS_TILE(0);
    __syncthreads();

    int buf = 0;
    for (int t = 0; t < ktiles; t++) {
        if (t + 1 < ktiles) LDG_TILE((t + 1) * BK);
#pragma unroll
        for (int kk = 0; kk < BK; kk++) {
            float4 a0 = *(const float4*)&As[buf][kk][ty * 8];
            float4 a1 = *(const float4*)&As[buf][kk][ty * 8 + 4];
            float4 b0 = *(const float4*)&Bs[buf][kk][tx * 8];
            float4 b1 = *(const float4*)&Bs[buf][kk][tx * 8 + 4];
            float va[8] = {a0.x, a0.y, a0.z, a0.w, a1.x, a1.y, a1.z, a1.w};
            float vb[8] = {b0.x, b0.y, b0.z, b0.w, b1.x, b1.y, b1.z, b1.w};
#pragma unroll
            for (int i = 0; i < 8; i++)
#pragma unroll
                for (int j = 0; j < 8; j++)
                    acc[i][j] += va[i] * vb[j];
        }
        if (t + 1 < ktiles) {
            STS_TILE(buf ^ 1);
            __syncthreads();
            buf ^= 1;
        }
    }

#pragma unroll
    for (int i = 0; i < 8; i++) {
        const long long m = m0 + ty * 8 + i;
        float4 o0, o1;
        o0.x = acc[i][0]; o0.y = acc[i][1]; o0.z = acc[i][2]; o0.w = acc[i][3];
        o1.x = acc[i][4]; o1.y = acc[i][5]; o1.z = acc[i][6]; o1.w = acc[i][7];
        *(float4*)(C + m * ldc + n0 + tx * 8)     = o0;
        *(float4*)(C + m * ldc + n0 + tx * 8 + 4) = o1;
    }
#undef LDG_TILE
#undef STS_TILE
}

// ---------------- RoPE (in place on q,k slices of g_qkv) ----------------------
__global__ void __launch_bounds__(1024) rope_kernel(float* __restrict__ qkv)
{
    __shared__ float s_inv[64];
    const int s = blockIdx.x;
    const int t = threadIdx.x;
    if (t < 64) {
        s_inv[t] = (float)pow(10000.0, -(double)(2 * t) / 128.0);
    }
    __syncthreads();

    const int h = t >> 6;      // 0..15
    const int j = t & 63;      // 0..63

    const float ang = (float)((double)s * (double)s_inv[j]);
    float sn, cs;
    sincosf(ang, &sn, &cs);

    float* q = qkv + (long long)s * E3 + h * HD;
    float* k = q + D_MODEL;

    const float q1 = q[j], q2 = q[j + 64];
    q[j]      = q1 * cs - q2 * sn;
    q[j + 64] = q2 * cs + q1 * sn;

    const float k1 = k[j], k2 = k[j + 64];
    k[j]      = k1 * cs - k2 * sn;
    k[j + 64] = k2 * cs + k1 * sn;
}

// ---------------- row softmax on scores (float4 vectorized) -------------------
__global__ void __launch_bounds__(256) softmax_kernel(float* __restrict__ scores)
{
    const long long row = blockIdx.x;
    float* p = scores + row * S_LEN;
    const int t = threadIdx.x;
    const int lane = t & 31, warp = t >> 5;

    __shared__ float red[8];

    float4 u0 = ((const float4*)p)[t * 2];
    float4 u1 = ((const float4*)p)[t * 2 + 1];
    float v[8] = {u0.x, u0.y, u0.z, u0.w, u1.x, u1.y, u1.z, u1.w};

    float mx = -INFINITY;
#pragma unroll
    for (int i = 0; i < 8; i++) mx = fmaxf(mx, v[i]);
#pragma unroll
    for (int o = 16; o; o >>= 1) mx = fmaxf(mx, __shfl_xor_sync(0xffffffffu, mx, o));
    if (lane == 0) red[warp] = mx;
    __syncthreads();
    if (t < 32) {
        float x = (t < 8) ? red[t] : -INFINITY;
#pragma unroll
        for (int o = 4; o; o >>= 1) x = fmaxf(x, __shfl_xor_sync(0xffffffffu, x, o));
        if (t == 0) red[0] = x;
    }
    __syncthreads();
    mx = red[0];
    __syncthreads();

    float sum = 0.0f;
#pragma unroll
    for (int i = 0; i < 8; i++) {
        v[i] = __expf(v[i] - mx);
        sum += v[i];
    }
#pragma unroll
    for (int o = 16; o; o >>= 1) sum += __shfl_xor_sync(0xffffffffu, sum, o);
    if (lane == 0) red[warp] = sum;
    __syncthreads();
    if (t < 32) {
        float x = (t < 8) ? red[t] : 0.0f;
#pragma unroll
        for (int o = 4; o; o >>= 1) x += __shfl_xor_sync(0xffffffffu, x, o);
        if (t == 0) red[0] = x;
    }
    __syncthreads();
    const float r = 1.0f / red[0];
    u0.x = v[0] * r; u0.y = v[1] * r; u0.z = v[2] * r; u0.w = v[3] * r;
    u1.x = v[4] * r; u1.y = v[5] * r; u1.z = v[6] * r; u1.w = v[7] * r;
    ((float4*)p)[t * 2]     = u0;
    ((float4*)p)[t * 2 + 1] = u1;
}

// ---------------- launch -------------------------------------------------------
extern "C" void kernel_launch(void* const* d_in, const int* in_sizes, int n_in,
                              void* d_out, int out_size)
{
    (void)in_sizes; (void)n_in; (void)out_size;
    const float* x     = (const float*)d_in[0];   // [1, 2048, 2048]
    const float* w_qkv = (const float*)d_in[1];   // [6144, 2048]
    const float* w_out = (const float*)d_in[2];   // [2048, 2048]
    float* out = (float*)d_out;                   // [1, 2048, 2048]

    float* qkv;    cudaGetSymbolAddress((void**)&qkv,    g_qkv);
    float* scores; cudaGetSymbolAddress((void**)&scores, g_scores);
    float* att;    cudaGetSymbolAddress((void**)&att,    g_att);

    const float scale = 0.08838834764831845f;  // 1/sqrt(128)

    // 1) QKV projection: qkv[s,e] = sum_d x[s,d] * w_qkv[e,d]
    {
        dim3 grid(E3 / 128, S_LEN / 128, 1);
        gemm_nt_kernel<<<grid, 256>>>(x, w_qkv, qkv,
                                      D_MODEL, D_MODEL, D_MODEL, E3,
                                      0, 0, 0, 1.0f);
    }

    // 2) RoPE on q and k (in place)
    rope_kernel<<<S_LEN, 1024>>>(qkv);

    // 3) scores[h][q,k] = scale * sum_d Q_h[q,d] * K_h[k,d]
    {
        dim3 grid(S_LEN / 128, S_LEN / 128, N_HEADS);
        gemm_nt_kernel<<<grid, 256>>>(qkv, qkv + D_MODEL, scores,
                                      HD, E3, E3, S_LEN,
                                      HD, HD, (long long)S_LEN * S_LEN, scale);
    }

    // 4) softmax over last dim
    softmax_kernel<<<N_HEADS * S_LEN, 256>>>(scores);

    // 5) att_h = P_h @ V_h  -> att[s, h*128 + d]
    {
        dim3 grid(HD / 128, S_LEN / 128, N_HEADS);
        gemm_nn_kernel<<<grid, 256>>>(scores, qkv + 2 * D_MODEL, att,
                                      S_LEN, S_LEN, E3, D_MODEL,
                                      (long long)S_LEN * S_LEN, HD, HD);
    }

    // 6) out[s,o] = sum_d att[s,d] * w_out[o,d]
    {
        dim3 grid(D_MODEL / 128, S_LEN / 128, 1);
        gemm_nt_kernel<<<grid, 256>>>(att, w_out, out,
                                      D_MODEL, D_MODEL, D_MODEL, D_MODEL,
                                      0, 0, 0, 1.0f);
    }
}

// round 4
// speedup vs baseline: 3.2450x; 2.2939x over previous
#include <cuda_runtime.h>
#include <cuda_bf16.h>
#include <math.h>
#include <stdint.h>

#define S_LEN 2048
#define D_MODEL 2048
#define N_HEADS 16
#define HD 128
#define E3 (3 * D_MODEL)   // 6144

// ---------------- scratch (static device globals; no allocations) -------------
__device__ float g_qkv[(size_t)S_LEN * E3];                      // fp32 qkv
__device__ float g_scores[(size_t)N_HEADS * S_LEN * S_LEN];      // fp32 logits
__device__ float g_att[(size_t)S_LEN * D_MODEL];                 // fp32 attention out

__device__ __nv_bfloat16 g_xh[(size_t)S_LEN * D_MODEL],  g_xl[(size_t)S_LEN * D_MODEL];
__device__ __nv_bfloat16 g_wqh[(size_t)E3 * D_MODEL],    g_wql[(size_t)E3 * D_MODEL];
__device__ __nv_bfloat16 g_woh[(size_t)D_MODEL * D_MODEL], g_wol[(size_t)D_MODEL * D_MODEL];
__device__ __nv_bfloat16 g_qh[(size_t)S_LEN * D_MODEL],  g_ql[(size_t)S_LEN * D_MODEL];
__device__ __nv_bfloat16 g_kh[(size_t)S_LEN * D_MODEL],  g_kl[(size_t)S_LEN * D_MODEL];
__device__ __nv_bfloat16 g_vth[(size_t)D_MODEL * S_LEN], g_vtl[(size_t)D_MODEL * S_LEN];
__device__ __nv_bfloat16 g_ath[(size_t)S_LEN * D_MODEL], g_atl[(size_t)S_LEN * D_MODEL];
__device__ __nv_bfloat16 g_ph[(size_t)N_HEADS * S_LEN * S_LEN], g_pl[(size_t)N_HEADS * S_LEN * S_LEN];

// =============================================================================
// helpers (base-ISA only: mma.sync / ldmatrix / cp.async — no tcgen05)
// =============================================================================
__device__ __forceinline__ uint32_t smem_u32(const void* p) {
    uint32_t a;
    asm("{ .reg .u64 t; cvta.to.shared.u64 t, %1; cvt.u32.u64 %0, t; }" : "=r"(a) : "l"(p));
    return a;
}
__device__ __forceinline__ void cp16(uint32_t dst, const void* src) {
    asm volatile("cp.async.cg.shared.global [%0], [%1], 16;" :: "r"(dst), "l"(src));
}
#define CP_COMMIT() asm volatile("cp.async.commit_group;" ::: "memory")
#define CP_WAIT(n)  asm volatile("cp.async.wait_group %0;" :: "n"(n) : "memory")

__device__ __forceinline__ void ldm4(uint32_t* r, uint32_t addr) {
    asm volatile("ldmatrix.sync.aligned.m8n8.x4.shared.b16 {%0,%1,%2,%3}, [%4];"
                 : "=r"(r[0]), "=r"(r[1]), "=r"(r[2]), "=r"(r[3]) : "r"(addr));
}
__device__ __forceinline__ void mma16816(float* d, const uint32_t* a, uint32_t b0, uint32_t b1) {
    asm volatile(
        "mma.sync.aligned.m16n8k16.row.col.f32.bf16.bf16.f32 "
        "{%0,%1,%2,%3}, {%4,%5,%6,%7}, {%8,%9}, {%0,%1,%2,%3};"
        : "+f"(d[0]), "+f"(d[1]), "+f"(d[2]), "+f"(d[3])
        : "r"(a[0]), "r"(a[1]), "r"(a[2]), "r"(a[3]), "r"(b0), "r"(b1));
}

__device__ __forceinline__ void split2(float x, __nv_bfloat16& h, __nv_bfloat16& l) {
    h = __float2bfloat16(x);
    l = __float2bfloat16(x - __bfloat162float(h));
}

// =============================================================================
// split-bf16 NT GEMM on HMMA (mma.sync): C[m,n] = scale * sum_k A[m,k]*B[n,k]
// A = Ah+Al, B = Bh+Bl. CTA tile 128x128, K-tile 64, cp.async double buffer.
// 8 warps: warp (wm 0..3, wn 0..1) owns 32(m) x 64(n).
// =============================================================================
#define TILE_B 16384                 // 128 rows * 64 bf16 * 2B
#define STAGE_B (4 * TILE_B)         // Ah, Al, Bh, Bl
#define GEMM_SMEM (2 * STAGE_B)      // 128 KB double buffered

__global__ void __launch_bounds__(256, 1) gemm_tc_kernel(
    const __nv_bfloat16* __restrict__ Ah, const __nv_bfloat16* __restrict__ Al,
    const __nv_bfloat16* __restrict__ Bh, const __nv_bfloat16* __restrict__ Bl,
    float* __restrict__ C, int K, int lda, int ldb, int ldc,
    long long aZ, long long bZ, long long cZ, float scale)
{
    extern __shared__ __align__(128) char smem[];
    const uint32_t sb = smem_u32(smem);
    const int tid = threadIdx.x;
    const int lane = tid & 31;
    const int wid = tid >> 5;
    const int wm = wid >> 1;          // 0..3 -> m offset 32*wm
    const int wn = wid & 1;           // 0..1 -> n offset 64*wn

    Ah += blockIdx.z * aZ;  Al += blockIdx.z * aZ;
    Bh += blockIdx.z * bZ;  Bl += blockIdx.z * bZ;
    C  += blockIdx.z * cZ;
    const int m0 = blockIdx.y * 128;
    const int n0 = blockIdx.x * 128;

    // per-thread global->smem mapping: 4 x 16B chunks per tile
    const int grow = tid >> 1;                 // reused via cid below
    (void)grow;

    float acc[2][8][4];
#pragma unroll
    for (int a = 0; a < 2; a++)
#pragma unroll
        for (int b = 0; b < 8; b++)
#pragma unroll
            for (int c = 0; c < 4; c++) acc[a][b][c] = 0.0f;

    const int nt = K / 64;

    // ---- stage loader ----
    auto load_stage = [&](int t, int buf) {
        const uint32_t base = sb + (uint32_t)buf * STAGE_B;
#pragma unroll
        for (int i = 0; i < 4; i++) {
            const int cid = tid + 256 * i;     // 0..1023
            const int row = cid >> 3;          // 0..127
            const int c   = cid & 7;           // 16B chunk in 128B row
            const uint32_t phys = (uint32_t)(row * 128 + ((c ^ (row & 7)) << 4));
            const size_t ga = (size_t)(m0 + row) * lda + (size_t)t * 64 + c * 8;
            const size_t gb = (size_t)(n0 + row) * ldb + (size_t)t * 64 + c * 8;
            cp16(base + 0 * TILE_B + phys, Ah + ga);
            cp16(base + 1 * TILE_B + phys, Al + ga);
            cp16(base + 2 * TILE_B + phys, Bh + gb);
            cp16(base + 3 * TILE_B + phys, Bl + gb);
        }
        CP_COMMIT();
    };

    load_stage(0, 0);

    for (int t = 0; t < nt; t++) {
        const int buf = t & 1;
        if (t + 1 < nt) {
            load_stage(t + 1, buf ^ 1);
            CP_WAIT(1);
        } else {
            CP_WAIT(0);
        }
        __syncthreads();

        const uint32_t tb = sb + (uint32_t)buf * STAGE_B;
#pragma unroll
        for (int k16 = 0; k16 < 4; k16++) {
            const int cb = k16 * 2 + (lane >> 4);     // 16B chunk base for this frag
            uint32_t ah[2][4], al[2][4];
            const int ar = wm * 32 + (lane & 15);
#pragma unroll
            for (int mb = 0; mb < 2; mb++) {
                const int R = ar + mb * 16;
                const uint32_t phys = (uint32_t)(R * 128 + ((cb ^ (R & 7)) << 4));
                ldm4(ah[mb], tb + 0 * TILE_B + phys);
                ldm4(al[mb], tb + 1 * TILE_B + phys);
            }
            uint32_t bh[4][4], bl[4][4];
            const int br = wn * 64 + (lane & 15);
#pragma unroll
            for (int q = 0; q < 4; q++) {
                const int R = br + q * 16;
                const uint32_t phys = (uint32_t)(R * 128 + ((cb ^ (R & 7)) << 4));
                ldm4(bh[q], tb + 2 * TILE_B + phys);
                ldm4(bl[q], tb + 3 * TILE_B + phys);
            }
#pragma unroll
            for (int mb = 0; mb < 2; mb++) {
#pragma unroll
                for (int q = 0; q < 4; q++) {
                    // n-block 2q   uses frag regs {0,2}; n-block 2q+1 uses {1,3}
                    mma16816(acc[mb][2 * q],     ah[mb], bh[q][0], bh[q][2]);
                    mma16816(acc[mb][2 * q],     ah[mb], bl[q][0], bl[q][2]);
                    mma16816(acc[mb][2 * q],     al[mb], bh[q][0], bh[q][2]);
                    mma16816(acc[mb][2 * q + 1], ah[mb], bh[q][1], bh[q][3]);
                    mma16816(acc[mb][2 * q + 1], ah[mb], bl[q][1], bl[q][3]);
                    mma16816(acc[mb][2 * q + 1], al[mb], bh[q][1], bh[q][3]);
                }
            }
        }
        __syncthreads();
    }

    // ---- epilogue: c-frag -> gmem fp32 ----
    const int g  = lane >> 2;
    const int tg = lane & 3;
#pragma unroll
    for (int mb = 0; mb < 2; mb++) {
        const int row = m0 + wm * 32 + mb * 16 + g;
#pragma unroll
        for (int nb = 0; nb < 8; nb++) {
            const int col = n0 + wn * 64 + nb * 8 + tg * 2;
            float2 v0, v1;
            v0.x = acc[mb][nb][0] * scale; v0.y = acc[mb][nb][1] * scale;
            v1.x = acc[mb][nb][2] * scale; v1.y = acc[mb][nb][3] * scale;
            *(float2*)(C + (size_t)row * ldc + col)       = v0;
            *(float2*)(C + (size_t)(row + 8) * ldc + col) = v1;
        }
    }
}

// =============================================================================
// split kernel: fp32 -> (hi, lo) bf16
// =============================================================================
__global__ void __launch_bounds__(256) split_kernel(
    const float* __restrict__ src, __nv_bfloat16* __restrict__ dh,
    __nv_bfloat16* __restrict__ dl, long long n4)
{
    const long long i = (long long)blockIdx.x * 256 + threadIdx.x;
    if (i >= n4) return;
    float4 v = ((const float4*)src)[i];
    __align__(8) __nv_bfloat16 hb[4], lb[4];
    split2(v.x, hb[0], lb[0]); split2(v.y, hb[1], lb[1]);
    split2(v.z, hb[2], lb[2]); split2(v.w, hb[3], lb[3]);
    ((uint2*)dh)[i] = *(uint2*)hb;
    ((uint2*)dl)[i] = *(uint2*)lb;
}

// =============================================================================
// RoPE + split: reads q,k from qkv fp32, writes qh/ql/kh/kl bf16
// =============================================================================
__global__ void __launch_bounds__(1024) rope_split_kernel(
    const float* __restrict__ qkv,
    __nv_bfloat16* __restrict__ qh, __nv_bfloat16* __restrict__ ql,
    __nv_bfloat16* __restrict__ kh, __nv_bfloat16* __restrict__ kl)
{
    __shared__ float s_inv[64];
    const int s = blockIdx.x;
    const int t = threadIdx.x;
    if (t < 64) s_inv[t] = (float)pow(10000.0, -(double)(2 * t) / 128.0);
    __syncthreads();

    const int h = t >> 6;
    const int j = t & 63;
    const float ang = (float)((double)s * (double)s_inv[j]);
    float sn, cs;
    sincosf(ang, &sn, &cs);

    const float* q = qkv + (size_t)s * E3 + h * HD;
    const float* k = q + D_MODEL;
    const size_t ob = (size_t)s * D_MODEL + h * HD;

    const float q1 = q[j], q2 = q[j + 64];
    const float k1 = k[j], k2 = k[j + 64];
    __nv_bfloat16 hh, ll;
    split2(q1 * cs - q2 * sn, hh, ll); qh[ob + j] = hh;      ql[ob + j] = ll;
    split2(q2 * cs + q1 * sn, hh, ll); qh[ob + j + 64] = hh; ql[ob + j + 64] = ll;
    split2(k1 * cs - k2 * sn, hh, ll); kh[ob + j] = hh;      kl[ob + j] = ll;
    split2(k2 * cs + k1 * sn, hh, ll); kh[ob + j + 64] = hh; kl[ob + j + 64] = ll;
}

// =============================================================================
// V transpose + split: vt[c][s] = qkv[s][2D + c]
// =============================================================================
__global__ void __launch_bounds__(256) vtrans_split_kernel(
    const float* __restrict__ qkv,
    __nv_bfloat16* __restrict__ vth, __nv_bfloat16* __restrict__ vtl)
{
    __shared__ float tile[32][33];
    const int c0 = blockIdx.x * 32;
    const int s0 = blockIdx.y * 32;
    const int tx = threadIdx.x & 31;
    const int ty = threadIdx.x >> 5;   // 0..7

#pragma unroll
    for (int r = ty; r < 32; r += 8)
        tile[r][tx] = qkv[(size_t)(s0 + r) * E3 + 2 * D_MODEL + c0 + tx];
    __syncthreads();
#pragma unroll
    for (int r = ty; r < 32; r += 8) {
        const float v = tile[tx][r];
        __nv_bfloat16 hh, ll;
        split2(v, hh, ll);
        const size_t o = (size_t)(c0 + r) * S_LEN + s0 + tx;
        vth[o] = hh;
        vtl[o] = ll;
    }
}

// =============================================================================
// softmax: reads fp32 scores row, writes bf16 split probabilities
// =============================================================================
__global__ void __launch_bounds__(256) softmax_kernel(
    const float* __restrict__ scores,
    __nv_bfloat16* __restrict__ ph, __nv_bfloat16* __restrict__ pl)
{
    const long long row = blockIdx.x;
    const float* p = scores + row * S_LEN;
    const int t = threadIdx.x;
    const int lane = t & 31, warp = t >> 5;

    __shared__ float red[8];

    float4 u0 = ((const float4*)p)[t * 2];
    float4 u1 = ((const float4*)p)[t * 2 + 1];
    float v[8] = {u0.x, u0.y, u0.z, u0.w, u1.x, u1.y, u1.z, u1.w};

    float mx = -INFINITY;
#pragma unroll
    for (int i = 0; i < 8; i++) mx = fmaxf(mx, v[i]);
#pragma unroll
    for (int o = 16; o; o >>= 1) mx = fmaxf(mx, __shfl_xor_sync(0xffffffffu, mx, o));
    if (lane == 0) red[warp] = mx;
    __syncthreads();
    if (t < 32) {
        float x = (t < 8) ? red[t] : -INFINITY;
#pragma unroll
        for (int o = 4; o; o >>= 1) x = fmaxf(x, __shfl_xor_sync(0xffffffffu, x, o));
        if (t == 0) red[0] = x;
    }
    __syncthreads();
    mx = red[0];
    __syncthreads();

    float sum = 0.0f;
#pragma unroll
    for (int i = 0; i < 8; i++) {
        v[i] = __expf(v[i] - mx);
        sum += v[i];
    }
#pragma unroll
    for (int o = 16; o; o >>= 1) sum += __shfl_xor_sync(0xffffffffu, sum, o);
    if (lane == 0) red[warp] = sum;
    __syncthreads();
    if (t < 32) {
        float x = (t < 8) ? red[t] : 0.0f;
#pragma unroll
        for (int o = 4; o; o >>= 1) x += __shfl_xor_sync(0xffffffffu, x, o);
        if (t == 0) red[0] = x;
    }
    __syncthreads();
    const float r = 1.0f / red[0];

    __align__(16) __nv_bfloat16 hb[8], lb[8];
#pragma unroll
    for (int i = 0; i < 8; i++) split2(v[i] * r, hb[i], lb[i]);
    const size_t ob = (size_t)row * S_LEN + (size_t)t * 8;
    *(uint4*)(ph + ob) = *(uint4*)hb;
    *(uint4*)(pl + ob) = *(uint4*)lb;
}

// =============================================================================
// launch
// =============================================================================
extern "C" void kernel_launch(void* const* d_in, const int* in_sizes, int n_in,
                              void* d_out, int out_size)
{
    (void)in_sizes; (void)n_in; (void)out_size;
    const float* x     = (const float*)d_in[0];   // [1, 2048, 2048]
    const float* w_qkv = (const float*)d_in[1];   // [6144, 2048]
    const float* w_out = (const float*)d_in[2];   // [2048, 2048]
    float* out = (float*)d_out;                   // [1, 2048, 2048]

    float *qkv, *scores, *att;
    cudaGetSymbolAddress((void**)&qkv,    g_qkv);
    cudaGetSymbolAddress((void**)&scores, g_scores);
    cudaGetSymbolAddress((void**)&att,    g_att);
    __nv_bfloat16 *xh, *xl, *wqh, *wql, *woh, *wol, *qh, *ql, *kh, *kl;
    __nv_bfloat16 *vth, *vtl, *ath, *atl, *ph, *pl;
    cudaGetSymbolAddress((void**)&xh,  g_xh);  cudaGetSymbolAddress((void**)&xl,  g_xl);
    cudaGetSymbolAddress((void**)&wqh, g_wqh); cudaGetSymbolAddress((void**)&wql, g_wql);
    cudaGetSymbolAddress((void**)&woh, g_woh); cudaGetSymbolAddress((void**)&wol, g_wol);
    cudaGetSymbolAddress((void**)&qh,  g_qh);  cudaGetSymbolAddress((void**)&ql,  g_ql);
    cudaGetSymbolAddress((void**)&kh,  g_kh);  cudaGetSymbolAddress((void**)&kl,  g_kl);
    cudaGetSymbolAddress((void**)&vth, g_vth); cudaGetSymbolAddress((void**)&vtl, g_vtl);
    cudaGetSymbolAddress((void**)&ath, g_ath); cudaGetSymbolAddress((void**)&atl, g_atl);
    cudaGetSymbolAddress((void**)&ph,  g_ph);  cudaGetSymbolAddress((void**)&pl,  g_pl);

    cudaFuncSetAttribute(gemm_tc_kernel, cudaFuncAttributeMaxDynamicSharedMemorySize, GEMM_SMEM);

    const float scale = 0.08838834764831845f;  // 1/sqrt(128)

    // 0) split inputs
    {
        long long n4;
        n4 = (long long)S_LEN * D_MODEL / 4;
        split_kernel<<<(unsigned)((n4 + 255) / 256), 256>>>(x, xh, xl, n4);
        n4 = (long long)E3 * D_MODEL / 4;
        split_kernel<<<(unsigned)((n4 + 255) / 256), 256>>>(w_qkv, wqh, wql, n4);
        n4 = (long long)D_MODEL * D_MODEL / 4;
        split_kernel<<<(unsigned)((n4 + 255) / 256), 256>>>(w_out, woh, wol, n4);
    }

    // 1) QKV projection: qkv[s,e] = sum_d x[s,d] * w_qkv[e,d]
    {
        dim3 grid(E3 / 128, S_LEN / 128, 1);
        gemm_tc_kernel<<<grid, 256, GEMM_SMEM>>>(xh, xl, wqh, wql, qkv,
                                                 D_MODEL, D_MODEL, D_MODEL, E3,
                                                 0, 0, 0, 1.0f);
    }

    // 2) RoPE + split q,k ; transpose + split v
    rope_split_kernel<<<S_LEN, 1024>>>(qkv, qh, ql, kh, kl);
    {
        dim3 grid(D_MODEL / 32, S_LEN / 32, 1);
        vtrans_split_kernel<<<grid, 256>>>(qkv, vth, vtl);
    }

    // 3) scores[h][q,k] = scale * sum_d Q_h[q,d] * K_h[k,d]
    {
        dim3 grid(S_LEN / 128, S_LEN / 128, N_HEADS);
        gemm_tc_kernel<<<grid, 256, GEMM_SMEM>>>(qh, ql, kh, kl, scores,
                                                 HD, D_MODEL, D_MODEL, S_LEN,
                                                 HD, HD, (long long)S_LEN * S_LEN, scale);
    }

    // 4) softmax -> split bf16 probabilities
    softmax_kernel<<<N_HEADS * S_LEN, 256>>>(scores, ph, pl);

    // 5) att[q, h*128+d] = sum_k P_h[q,k] * Vt_h[d,k]
    {
        dim3 grid(1, S_LEN / 128, N_HEADS);
        gemm_tc_kernel<<<grid, 256, GEMM_SMEM>>>(ph, pl, vth, vtl, att,
                                                 S_LEN, S_LEN, S_LEN, D_MODEL,
                                                 (long long)S_LEN * S_LEN,
                                                 (long long)HD * S_LEN,
                                                 (long long)HD, 1.0f);
    }

    // 5b) split att
    {
        long long n4 = (long long)S_LEN * D_MODEL / 4;
        split_kernel<<<(unsigned)((n4 + 255) / 256), 256>>>(att, ath, atl, n4);
    }

    // 6) out[s,o] = sum_d att[s,d] * w_out[o,d]
    {
        dim3 grid(D_MODEL / 128, S_LEN / 128, 1);
        gemm_tc_kernel<<<grid, 256, GEMM_SMEM>>>(ath, atl, woh, wol, out,
                                                 D_MODEL, D_MODEL, D_MODEL, D_MODEL,
                                                 0, 0, 0, 1.0f);
    }
}

// round 5
// speedup vs baseline: 3.2485x; 1.0011x over previous
#include <cuda_runtime.h>
#include <cuda_bf16.h>
#include <math.h>
#include <stdint.h>

#define S_LEN 2048
#define D_MODEL 2048
#define N_HEADS 16
#define HD 128
#define E3 (3 * D_MODEL)   // 6144

// ---------------- scratch (static device globals; no allocations) -------------
__device__ float g_qkv[(size_t)S_LEN * E3];                      // fp32 qkv
__device__ float g_scores[(size_t)N_HEADS * S_LEN * S_LEN];      // fp32 logits

__device__ __nv_bfloat16 g_xh[(size_t)S_LEN * D_MODEL],  g_xl[(size_t)S_LEN * D_MODEL];
__device__ __nv_bfloat16 g_wqh[(size_t)E3 * D_MODEL],    g_wql[(size_t)E3 * D_MODEL];
__device__ __nv_bfloat16 g_woh[(size_t)D_MODEL * D_MODEL], g_wol[(size_t)D_MODEL * D_MODEL];
__device__ __nv_bfloat16 g_qh[(size_t)S_LEN * D_MODEL],  g_ql[(size_t)S_LEN * D_MODEL];
__device__ __nv_bfloat16 g_kh[(size_t)S_LEN * D_MODEL],  g_kl[(size_t)S_LEN * D_MODEL];
__device__ __nv_bfloat16 g_vth[(size_t)D_MODEL * S_LEN], g_vtl[(size_t)D_MODEL * S_LEN];
__device__ __nv_bfloat16 g_ath[(size_t)S_LEN * D_MODEL], g_atl[(size_t)S_LEN * D_MODEL];
__device__ __nv_bfloat16 g_ph[(size_t)N_HEADS * S_LEN * S_LEN], g_pl[(size_t)N_HEADS * S_LEN * S_LEN];

// =============================================================================
// helpers (base-ISA only: mma.sync / ldmatrix / cp.async — no tcgen05)
// =============================================================================
__device__ __forceinline__ uint32_t smem_u32(const void* p) {
    uint32_t a;
    asm("{ .reg .u64 t; cvta.to.shared.u64 t, %1; cvt.u32.u64 %0, t; }" : "=r"(a) : "l"(p));
    return a;
}
__device__ __forceinline__ void cp16(uint32_t dst, const void* src) {
    asm volatile("cp.async.cg.shared.global [%0], [%1], 16;" :: "r"(dst), "l"(src));
}
#define CP_COMMIT() asm volatile("cp.async.commit_group;" ::: "memory")
#define CP_WAIT(n)  asm volatile("cp.async.wait_group %0;" :: "n"(n) : "memory")

__device__ __forceinline__ void ldm4(uint32_t* r, uint32_t addr) {
    asm volatile("ldmatrix.sync.aligned.m8n8.x4.shared.b16 {%0,%1,%2,%3}, [%4];"
                 : "=r"(r[0]), "=r"(r[1]), "=r"(r[2]), "=r"(r[3]) : "r"(addr));
}
__device__ __forceinline__ void mma16816(float* d, const uint32_t* a, uint32_t b0, uint32_t b1) {
    asm volatile(
        "mma.sync.aligned.m16n8k16.row.col.f32.bf16.bf16.f32 "
        "{%0,%1,%2,%3}, {%4,%5,%6,%7}, {%8,%9}, {%0,%1,%2,%3};"
        : "+f"(d[0]), "+f"(d[1]), "+f"(d[2]), "+f"(d[3])
        : "r"(a[0]), "r"(a[1]), "r"(a[2]), "r"(a[3]), "r"(b0), "r"(b1));
}

__device__ __forceinline__ void split2(float x, __nv_bfloat16& h, __nv_bfloat16& l) {
    h = __float2bfloat16(x);
    l = __float2bfloat16(x - __bfloat162float(h));
}
__device__ __forceinline__ uint32_t pack_split_hi(float a, float b) {
    __align__(4) __nv_bfloat16 t[2];
    __nv_bfloat16 l0, l1;
    split2(a, t[0], l0); split2(b, t[1], l1);
    (void)l0; (void)l1;
    return *(uint32_t*)t;
}
__device__ __forceinline__ void pack_split(float a, float b, uint32_t& hi, uint32_t& lo) {
    __align__(4) __nv_bfloat16 th[2], tl[2];
    split2(a, th[0], tl[0]); split2(b, th[1], tl[1]);
    hi = *(uint32_t*)th;
    lo = *(uint32_t*)tl;
}

// =============================================================================
// split-bf16 NT GEMM on HMMA (mma.sync): C[m,n] = scale * sum_k A[m,k]*B[n,k]
// A = Ah+Al, B = Bh+Bl. CTA tile 128x128, K-tile 64, cp.async double buffer.
// 512 threads, 16 warps: warp (wm 0..3, wn 0..3) owns 32(m) x 32(n).
// Epilogue: either fp32 C, or split bf16 (Ch, Cl).
// =============================================================================
#define TILE_B 16384                 // 128 rows * 64 bf16 * 2B
#define STAGE_B (4 * TILE_B)         // Ah, Al, Bh, Bl
#define GEMM_SMEM (2 * STAGE_B)      // 128 KB double buffered

__global__ void __launch_bounds__(512, 1) gemm_tc_kernel(
    const __nv_bfloat16* __restrict__ Ah, const __nv_bfloat16* __restrict__ Al,
    const __nv_bfloat16* __restrict__ Bh, const __nv_bfloat16* __restrict__ Bl,
    float* __restrict__ C, __nv_bfloat16* __restrict__ Ch, __nv_bfloat16* __restrict__ Cl,
    int K, int lda, int ldb, int ldc,
    long long aZ, long long bZ, long long cZ, float scale)
{
    extern __shared__ __align__(128) char smem[];
    const uint32_t sb = smem_u32(smem);
    const int tid = threadIdx.x;
    const int lane = tid & 31;
    const int wid = tid >> 5;
    const int wm = wid & 3;           // m offset 32*wm
    const int wn = wid >> 2;          // n offset 32*wn

    Ah += blockIdx.z * aZ;  Al += blockIdx.z * aZ;
    Bh += blockIdx.z * bZ;  Bl += blockIdx.z * bZ;
    const int m0 = blockIdx.y * 128;
    const int n0 = blockIdx.x * 128;

    float acc[2][4][4];
#pragma unroll
    for (int a = 0; a < 2; a++)
#pragma unroll
        for (int b = 0; b < 4; b++)
#pragma unroll
            for (int c = 0; c < 4; c++) acc[a][b][c] = 0.0f;

    const int nt = K / 64;

    // ---- stage loader: 512 threads, 2 chunk-iters x 4 tiles ----
    auto load_stage = [&](int t, int buf) {
        const uint32_t base = sb + (uint32_t)buf * STAGE_B;
#pragma unroll
        for (int i = 0; i < 2; i++) {
            const int cid = tid + 512 * i;     // 0..1023
            const int row = cid >> 3;          // 0..127
            const int c   = cid & 7;           // 16B chunk in 128B row
            const uint32_t phys = (uint32_t)(row * 128 + ((c ^ (row & 7)) << 4));
            const size_t ga = (size_t)(m0 + row) * lda + (size_t)t * 64 + c * 8;
            const size_t gb = (size_t)(n0 + row) * ldb + (size_t)t * 64 + c * 8;
            cp16(base + 0 * TILE_B + phys, Ah + ga);
            cp16(base + 1 * TILE_B + phys, Al + ga);
            cp16(base + 2 * TILE_B + phys, Bh + gb);
            cp16(base + 3 * TILE_B + phys, Bl + gb);
        }
        CP_COMMIT();
    };

    load_stage(0, 0);

    for (int t = 0; t < nt; t++) {
        const int buf = t & 1;
        if (t + 1 < nt) {
            load_stage(t + 1, buf ^ 1);
            CP_WAIT(1);
        } else {
            CP_WAIT(0);
        }
        __syncthreads();

        const uint32_t tb = sb + (uint32_t)buf * STAGE_B;
#pragma unroll
        for (int k16 = 0; k16 < 4; k16++) {
            const int cb = k16 * 2 + (lane >> 4);     // 16B chunk base for this frag
            uint32_t ah[2][4], al[2][4];
            const int ar = wm * 32 + (lane & 15);
#pragma unroll
            for (int mb = 0; mb < 2; mb++) {
                const int R = ar + mb * 16;
                const uint32_t phys = (uint32_t)(R * 128 + ((cb ^ (R & 7)) << 4));
                ldm4(ah[mb], tb + 0 * TILE_B + phys);
                ldm4(al[mb], tb + 1 * TILE_B + phys);
            }
            uint32_t bh[2][4], bl[2][4];
            const int br = wn * 32 + (lane & 15);
#pragma unroll
            for (int q = 0; q < 2; q++) {
                const int R = br + q * 16;
                const uint32_t phys = (uint32_t)(R * 128 + ((cb ^ (R & 7)) << 4));
                ldm4(bh[q], tb + 2 * TILE_B + phys);
                ldm4(bl[q], tb + 3 * TILE_B + phys);
            }
#pragma unroll
            for (int mb = 0; mb < 2; mb++) {
#pragma unroll
                for (int q = 0; q < 2; q++) {
                    // n-block 2q uses frag regs {0,2}; 2q+1 uses {1,3}
                    mma16816(acc[mb][2 * q],     ah[mb], bh[q][0], bh[q][2]);
                    mma16816(acc[mb][2 * q],     ah[mb], bl[q][0], bl[q][2]);
                    mma16816(acc[mb][2 * q],     al[mb], bh[q][0], bh[q][2]);
                    mma16816(acc[mb][2 * q + 1], ah[mb], bh[q][1], bh[q][3]);
                    mma16816(acc[mb][2 * q + 1], ah[mb], bl[q][1], bl[q][3]);
                    mma16816(acc[mb][2 * q + 1], al[mb], bh[q][1], bh[q][3]);
                }
            }
        }
        __syncthreads();
    }

    // ---- epilogue ----
    const int g  = lane >> 2;
    const int tg = lane & 3;
    if (C) {
        C += blockIdx.z * cZ;
#pragma unroll
        for (int mb = 0; mb < 2; mb++) {
            const int row = m0 + wm * 32 + mb * 16 + g;
#pragma unroll
            for (int nb = 0; nb < 4; nb++) {
                const int col = n0 + wn * 32 + nb * 8 + tg * 2;
                float2 v0, v1;
                v0.x = acc[mb][nb][0] * scale; v0.y = acc[mb][nb][1] * scale;
                v1.x = acc[mb][nb][2] * scale; v1.y = acc[mb][nb][3] * scale;
                *(float2*)(C + (size_t)row * ldc + col)       = v0;
                *(float2*)(C + (size_t)(row + 8) * ldc + col) = v1;
            }
        }
    } else {
        Ch += blockIdx.z * cZ;
        Cl += blockIdx.z * cZ;
#pragma unroll
        for (int mb = 0; mb < 2; mb++) {
            const int row = m0 + wm * 32 + mb * 16 + g;
#pragma unroll
            for (int nb = 0; nb < 4; nb++) {
                const int col = n0 + wn * 32 + nb * 8 + tg * 2;
                uint32_t h0, l0, h1, l1;
                pack_split(acc[mb][nb][0] * scale, acc[mb][nb][1] * scale, h0, l0);
                pack_split(acc[mb][nb][2] * scale, acc[mb][nb][3] * scale, h1, l1);
                *(uint32_t*)(Ch + (size_t)row * ldc + col)       = h0;
                *(uint32_t*)(Cl + (size_t)row * ldc + col)       = l0;
                *(uint32_t*)(Ch + (size_t)(row + 8) * ldc + col) = h1;
                *(uint32_t*)(Cl + (size_t)(row + 8) * ldc + col) = l1;
            }
        }
    }
}

// =============================================================================
// split kernel: fp32 -> (hi, lo) bf16
// =============================================================================
__global__ void __launch_bounds__(256) split_kernel(
    const float* __restrict__ src, __nv_bfloat16* __restrict__ dh,
    __nv_bfloat16* __restrict__ dl, long long n4)
{
    const long long i = (long long)blockIdx.x * 256 + threadIdx.x;
    if (i >= n4) return;
    float4 v = ((const float4*)src)[i];
    __align__(8) __nv_bfloat16 hb[4], lb[4];
    split2(v.x, hb[0], lb[0]); split2(v.y, hb[1], lb[1]);
    split2(v.z, hb[2], lb[2]); split2(v.w, hb[3], lb[3]);
    ((uint2*)dh)[i] = *(uint2*)hb;
    ((uint2*)dl)[i] = *(uint2*)lb;
}

// =============================================================================
// RoPE + split: reads q,k from qkv fp32, writes qh/ql/kh/kl bf16
// =============================================================================
__global__ void __launch_bounds__(1024) rope_split_kernel(
    const float* __restrict__ qkv,
    __nv_bfloat16* __restrict__ qh, __nv_bfloat16* __restrict__ ql,
    __nv_bfloat16* __restrict__ kh, __nv_bfloat16* __restrict__ kl)
{
    __shared__ float s_inv[64];
    const int s = blockIdx.x;
    const int t = threadIdx.x;
    if (t < 64) s_inv[t] = (float)pow(10000.0, -(double)(2 * t) / 128.0);
    __syncthreads();

    const int h = t >> 6;
    const int j = t & 63;
    const float ang = (float)((double)s * (double)s_inv[j]);
    float sn, cs;
    sincosf(ang, &sn, &cs);

    const float* q = qkv + (size_t)s * E3 + h * HD;
    const float* k = q + D_MODEL;
    const size_t ob = (size_t)s * D_MODEL + h * HD;

    const float q1 = q[j], q2 = q[j + 64];
    const float k1 = k[j], k2 = k[j + 64];
    __nv_bfloat16 hh, ll;
    split2(q1 * cs - q2 * sn, hh, ll); qh[ob + j] = hh;      ql[ob + j] = ll;
    split2(q2 * cs + q1 * sn, hh, ll); qh[ob + j + 64] = hh; ql[ob + j + 64] = ll;
    split2(k1 * cs - k2 * sn, hh, ll); kh[ob + j] = hh;      kl[ob + j] = ll;
    split2(k2 * cs + k1 * sn, hh, ll); kh[ob + j + 64] = hh; kl[ob + j + 64] = ll;
}

// =============================================================================
// V transpose + split: vt[c][s] = qkv[s][2D + c]
// =============================================================================
__global__ void __launch_bounds__(256) vtrans_split_kernel(
    const float* __restrict__ qkv,
    __nv_bfloat16* __restrict__ vth, __nv_bfloat16* __restrict__ vtl)
{
    __shared__ float tile[32][33];
    const int c0 = blockIdx.x * 32;
    const int s0 = blockIdx.y * 32;
    const int tx = threadIdx.x & 31;
    const int ty = threadIdx.x >> 5;   // 0..7

#pragma unroll
    for (int r = ty; r < 32; r += 8)
        tile[r][tx] = qkv[(size_t)(s0 + r) * E3 + 2 * D_MODEL + c0 + tx];
    __syncthreads();
#pragma unroll
    for (int r = ty; r < 32; r += 8) {
        const float v = tile[tx][r];
        __nv_bfloat16 hh, ll;
        split2(v, hh, ll);
        const size_t o = (size_t)(c0 + r) * S_LEN + s0 + tx;
        vth[o] = hh;
        vtl[o] = ll;
    }
}

// =============================================================================
// softmax: reads fp32 scores row, writes bf16 split probabilities
// =============================================================================
__global__ void __launch_bounds__(256) softmax_kernel(
    const float* __restrict__ scores,
    __nv_bfloat16* __restrict__ ph, __nv_bfloat16* __restrict__ pl)
{
    const long long row = blockIdx.x;
    const float* p = scores + row * S_LEN;
    const int t = threadIdx.x;
    const int lane = t & 31, warp = t >> 5;

    __shared__ float red[8];

    float4 u0 = ((const float4*)p)[t * 2];
    float4 u1 = ((const float4*)p)[t * 2 + 1];
    float v[8] = {u0.x, u0.y, u0.z, u0.w, u1.x, u1.y, u1.z, u1.w};

    float mx = -INFINITY;
#pragma unroll
    for (int i = 0; i < 8; i++) mx = fmaxf(mx, v[i]);
#pragma unroll
    for (int o = 16; o; o >>= 1) mx = fmaxf(mx, __shfl_xor_sync(0xffffffffu, mx, o));
    if (lane == 0) red[warp] = mx;
    __syncthreads();
    if (t < 32) {
        float x = (t < 8) ? red[t] : -INFINITY;
#pragma unroll
        for (int o = 4; o; o >>= 1) x = fmaxf(x, __shfl_xor_sync(0xffffffffu, x, o));
        if (t == 0) red[0] = x;
    }
    __syncthreads();
    mx = red[0];
    __syncthreads();

    float sum = 0.0f;
#pragma unroll
    for (int i = 0; i < 8; i++) {
        v[i] = __expf(v[i] - mx);
        sum += v[i];
    }
#pragma unroll
    for (int o = 16; o; o >>= 1) sum += __shfl_xor_sync(0xffffffffu, sum, o);
    if (lane == 0) red[warp] = sum;
    __syncthreads();
    if (t < 32) {
        float x = (t < 8) ? red[t] : 0.0f;
#pragma unroll
        for (int o = 4; o; o >>= 1) x += __shfl_xor_sync(0xffffffffu, x, o);
        if (t == 0) red[0] = x;
    }
    __syncthreads();
    const float r = 1.0f / red[0];

    __align__(16) __nv_bfloat16 hb[8], lb[8];
#pragma unroll
    for (int i = 0; i < 8; i++) split2(v[i] * r, hb[i], lb[i]);
    const size_t ob = (size_t)row * S_LEN + (size_t)t * 8;
    *(uint4*)(ph + ob) = *(uint4*)hb;
    *(uint4*)(pl + ob) = *(uint4*)lb;
}

// =============================================================================
// launch
// =============================================================================
extern "C" void kernel_launch(void* const* d_in, const int* in_sizes, int n_in,
                              void* d_out, int out_size)
{
    (void)in_sizes; (void)n_in; (void)out_size;
    const float* x     = (const float*)d_in[0];   // [1, 2048, 2048]
    const float* w_qkv = (const float*)d_in[1];   // [6144, 2048]
    const float* w_out = (const float*)d_in[2];   // [2048, 2048]
    float* out = (float*)d_out;                   // [1, 2048, 2048]

    float *qkv, *scores;
    cudaGetSymbolAddress((void**)&qkv,    g_qkv);
    cudaGetSymbolAddress((void**)&scores, g_scores);
    __nv_bfloat16 *xh, *xl, *wqh, *wql, *woh, *wol, *qh, *ql, *kh, *kl;
    __nv_bfloat16 *vth, *vtl, *ath, *atl, *ph, *pl;
    cudaGetSymbolAddress((void**)&xh,  g_xh);  cudaGetSymbolAddress((void**)&xl,  g_xl);
    cudaGetSymbolAddress((void**)&wqh, g_wqh); cudaGetSymbolAddress((void**)&wql, g_wql);
    cudaGetSymbolAddress((void**)&woh, g_woh); cudaGetSymbolAddress((void**)&wol, g_wol);
    cudaGetSymbolAddress((void**)&qh,  g_qh);  cudaGetSymbolAddress((void**)&ql,  g_ql);
    cudaGetSymbolAddress((void**)&kh,  g_kh);  cudaGetSymbolAddress((void**)&kl,  g_kl);
    cudaGetSymbolAddress((void**)&vth, g_vth); cudaGetSymbolAddress((void**)&vtl, g_vtl);
    cudaGetSymbolAddress((void**)&ath, g_ath); cudaGetSymbolAddress((void**)&atl, g_atl);
    cudaGetSymbolAddress((void**)&ph,  g_ph);  cudaGetSymbolAddress((void**)&pl,  g_pl);

    cudaFuncSetAttribute(gemm_tc_kernel, cudaFuncAttributeMaxDynamicSharedMemorySize, GEMM_SMEM);

    const float scale = 0.08838834764831845f;  // 1/sqrt(128)

    // 0) split inputs
    {
        long long n4;
        n4 = (long long)S_LEN * D_MODEL / 4;
        split_kernel<<<(unsigned)((n4 + 255) / 256), 256>>>(x, xh, xl, n4);
        n4 = (long long)E3 * D_MODEL / 4;
        split_kernel<<<(unsigned)((n4 + 255) / 256), 256>>>(w_qkv, wqh, wql, n4);
        n4 = (long long)D_MODEL * D_MODEL / 4;
        split_kernel<<<(unsigned)((n4 + 255) / 256), 256>>>(w_out, woh, wol, n4);
    }

    // 1) QKV projection: qkv[s,e] = sum_d x[s,d] * w_qkv[e,d]  (fp32 out)
    {
        dim3 grid(E3 / 128, S_LEN / 128, 1);
        gemm_tc_kernel<<<grid, 512, GEMM_SMEM>>>(xh, xl, wqh, wql, qkv, nullptr, nullptr,
                                                 D_MODEL, D_MODEL, D_MODEL, E3,
                                                 0, 0, 0, 1.0f);
    }

    // 2) RoPE + split q,k ; transpose + split v
    rope_split_kernel<<<S_LEN, 1024>>>(qkv, qh, ql, kh, kl);
    {
        dim3 grid(D_MODEL / 32, S_LEN / 32, 1);
        vtrans_split_kernel<<<grid, 256>>>(qkv, vth, vtl);
    }

    // 3) scores[h][q,k] = scale * sum_d Q_h[q,d] * K_h[k,d]  (fp32 out)
    {
        dim3 grid(S_LEN / 128, S_LEN / 128, N_HEADS);
        gemm_tc_kernel<<<grid, 512, GEMM_SMEM>>>(qh, ql, kh, kl, scores, nullptr, nullptr,
                                                 HD, D_MODEL, D_MODEL, S_LEN,
                                                 HD, HD, (long long)S_LEN * S_LEN, scale);
    }

    // 4) softmax -> split bf16 probabilities
    softmax_kernel<<<N_HEADS * S_LEN, 256>>>(scores, ph, pl);

    // 5) att[q, h*128+d] = sum_k P_h[q,k] * Vt_h[d,k]  (split bf16 out, fused)
    {
        dim3 grid(1, S_LEN / 128, N_HEADS);
        gemm_tc_kernel<<<grid, 512, GEMM_SMEM>>>(ph, pl, vth, vtl, nullptr, ath, atl,
                                                 S_LEN, S_LEN, S_LEN, D_MODEL,
                                                 (long long)S_LEN * S_LEN,
                                                 (long long)HD * S_LEN,
                                                 (long long)HD, 1.0f);
    }

    // 6) out[s,o] = sum_d att[s,d] * w_out[o,d]  (fp32 out)
    {
        dim3 grid(D_MODEL / 128, S_LEN / 128, 1);
        gemm_tc_kernel<<<grid, 512, GEMM_SMEM>>>(ath, atl, woh, wol, out, nullptr, nullptr,
                                                 D_MODEL, D_MODEL, D_MODEL, D_MODEL,
                                                 0, 0, 0, 1.0f);
    }
}